// round 1
// baseline (speedup 1.0000x reference)
#include <cuda_runtime.h>

// ---------------- problem constants ----------------
#define BATCH   16
#define C_IN    128
#define C_OUT   128
#define KS      3
#define HH      128
#define WW      128
#define HDIM    512
#define W_SIZE  (C_OUT * C_IN * KS * KS)   // 147456
#define OH      126
#define OW      126

// ---------------- scratch (no runtime allocation allowed) ----------------
__device__ float g_w[BATCH * W_SIZE];   // per-sample conv weights, 9.4 MB
__device__ float g_b[BATCH * C_OUT];    // per-sample bias

// ============================================================
// Kernel A: w[b][n] = bh[n] + sum_k h[b][k] * Wh[n][k]
// One thread per n, all 16 batches accumulated in registers.
// h lives in SMEM (broadcast reads). Each lane walks its own Wh
// row sequentially in float4 steps -> full L1 line reuse, so DRAM
// traffic == 302 MB exactly.
// ============================================================
__global__ void __launch_bounds__(256) hyper_w_kernel(
    const float* __restrict__ h,
    const float* __restrict__ Wh,
    const float* __restrict__ bh)
{
    __shared__ __align__(16) float4 hs[BATCH][HDIM / 4];

    const int tid = threadIdx.x;
    const float4* h4 = (const float4*)h;
    #pragma unroll
    for (int i = tid; i < BATCH * HDIM / 4; i += 256)
        ((float4*)hs)[i] = h4[i];
    __syncthreads();

    const int n = blockIdx.x * 256 + tid;          // W_SIZE % 256 == 0
    const float4* w4 = (const float4*)Wh + (size_t)n * (HDIM / 4);

    float acc[BATCH];
    #pragma unroll
    for (int b = 0; b < BATCH; ++b) acc[b] = 0.f;

    #pragma unroll 4
    for (int k = 0; k < HDIM / 4; ++k) {
        const float4 wv = w4[k];
        #pragma unroll
        for (int b = 0; b < BATCH; ++b) {
            const float4 hv = hs[b][k];
            acc[b] += hv.x * wv.x + hv.y * wv.y + hv.z * wv.z + hv.w * wv.w;
        }
    }

    const float bias = bh[n];
    #pragma unroll
    for (int b = 0; b < BATCH; ++b)
        g_w[(size_t)b * W_SIZE + n] = acc[b] + bias;
}

// ============================================================
// Kernel B: b[b][oc] = bb[oc] + sum_k h[b][k] * Wb[oc][k]
// Tiny: grid = 16 blocks x 128 threads.
// ============================================================
__global__ void __launch_bounds__(128) hyper_b_kernel(
    const float* __restrict__ h,
    const float* __restrict__ Wb,
    const float* __restrict__ bb)
{
    const int b  = blockIdx.x;
    const int oc = threadIdx.x;
    const float4* h4 = (const float4*)(h + b * HDIM);
    const float4* w4 = (const float4*)(Wb + oc * HDIM);
    float s = 0.f;
    #pragma unroll 4
    for (int k = 0; k < HDIM / 4; ++k) {
        const float4 a = h4[k];
        const float4 w = w4[k];
        s += a.x * w.x + a.y * w.y + a.z * w.z + a.w * w.w;
    }
    g_b[b * C_OUT + oc] = s + bb[oc];
}

// ============================================================
// Kernel C: direct 3x3 VALID conv (cross-correlation), per-sample weights.
// Block: 32 output channels x 16x16 output pixels for one sample.
// ic processed in chunks of 16 through SMEM.
// Thread register tile: 4 oc x 8 px (32 accumulators).
// ============================================================
#define TOC 32          // oc per block
#define TP  16          // output tile edge
#define ICC 16          // ic per chunk
#define IROW 20         // padded smem input row (18 used)

__global__ void __launch_bounds__(256) conv_kernel(
    const float* __restrict__ x,
    float* __restrict__ out)
{
    __shared__ __align__(16) float in_s[ICC][TP + 2][IROW];    // 16*18*20*4 = 23040 B
    __shared__ float w_s[TOC][ICC * 9];                        // 32*144*4  = 18432 B

    const int tid  = threadIdx.x;
    const int b    = blockIdx.z;
    const int oc0  = blockIdx.y * TOC;
    const int tile = blockIdx.x;              // 0..63
    const int oh0  = (tile >> 3) * TP;
    const int ow0  = (tile & 7) * TP;

    const int tx  = tid & 31;
    const int ty  = tid >> 5;                 // 0..7
    const int pr  = tx >> 1;                  // 0..15  (output row in tile)
    const int pc  = (tx & 1) * 8;             // 0 or 8 (output col base)
    const int ocb = ty * 4;                   // oc offset within tile

    float acc[4][8];
    #pragma unroll
    for (int j = 0; j < 4; ++j)
        #pragma unroll
        for (int p = 0; p < 8; ++p) acc[j][p] = 0.f;

    const float* xb = x + (size_t)b * C_IN * HH * WW;
    const float* wb = g_w + (size_t)b * W_SIZE;

    for (int ic0 = 0; ic0 < C_IN; ic0 += ICC) {
        __syncthreads();   // previous chunk's compute done before overwrite

        // ---- stage input halo tile: ICC x 18 x 18 (guarded, coalesced) ----
        #pragma unroll
        for (int i = tid; i < ICC * 18 * 18; i += 256) {
            const int ic  = i / 324;
            const int rem = i - ic * 324;
            const int r   = rem / 18;
            const int c   = rem - r * 18;
            const int ih  = oh0 + r;
            const int iw  = ow0 + c;
            float v = 0.f;
            if (ih < HH && iw < WW)
                v = xb[(size_t)(ic0 + ic) * (HH * WW) + ih * WW + iw];
            in_s[ic][r][c] = v;
        }

        // ---- stage weights: TOC x (ICC*9), layout matches global (coalesced,
        //      conflict-free stores; compute reads are warp-uniform broadcasts) ----
        #pragma unroll
        for (int i = tid; i < TOC * ICC * 9; i += 256) {
            const int oc  = i / (ICC * 9);
            const int rem = i - oc * (ICC * 9);
            w_s[oc][rem] = wb[(size_t)(oc0 + oc) * (C_IN * 9) + ic0 * 9 + rem];
        }
        __syncthreads();

        // ---- compute ----
        #pragma unroll
        for (int ic = 0; ic < ICC; ++ic) {
            #pragma unroll
            for (int r = 0; r < 3; ++r) {
                // 10 input values cover 8 outputs x 3 horizontal taps
                const float* row = &in_s[ic][pr + r][pc];
                const float4 a0 = *(const float4*)(row);
                const float4 a1 = *(const float4*)(row + 4);
                const float2 a2 = *(const float2*)(row + 8);
                const float iv[10] = { a0.x, a0.y, a0.z, a0.w,
                                       a1.x, a1.y, a1.z, a1.w,
                                       a2.x, a2.y };
                #pragma unroll
                for (int c = 0; c < 3; ++c) {
                    const int widx = ic * 9 + r * 3 + c;
                    const float w0 = w_s[ocb + 0][widx];
                    const float w1 = w_s[ocb + 1][widx];
                    const float w2 = w_s[ocb + 2][widx];
                    const float w3 = w_s[ocb + 3][widx];
                    #pragma unroll
                    for (int p = 0; p < 8; ++p) {
                        const float xv = iv[p + c];
                        acc[0][p] += xv * w0;
                        acc[1][p] += xv * w1;
                        acc[2][p] += xv * w2;
                        acc[3][p] += xv * w3;
                    }
                }
            }
        }
    }

    // ---- epilogue: bias + guarded store ----
    const int oh = oh0 + pr;
    if (oh < OH) {
        #pragma unroll
        for (int j = 0; j < 4; ++j) {
            const int oc = oc0 + ocb + j;
            const float bias = g_b[b * C_OUT + oc];
            float* op = out + (((size_t)b * C_OUT + oc) * OH + oh) * OW + ow0 + pc;
            #pragma unroll
            for (int p = 0; p < 8; ++p) {
                if (ow0 + pc + p < OW)
                    op[p] = acc[j][p] + bias;
            }
        }
    }
}

// ============================================================
// launch
// ============================================================
extern "C" void kernel_launch(void* const* d_in, const int* in_sizes, int n_in,
                              void* d_out, int out_size)
{
    const float* x  = (const float*)d_in[0];   // (16,128,128,128)
    const float* h  = (const float*)d_in[1];   // (16,512)
    const float* Wh = (const float*)d_in[2];   // (147456,512)
    const float* bh = (const float*)d_in[3];   // (147456,)
    const float* Wb = (const float*)d_in[4];   // (128,512)
    const float* bb = (const float*)d_in[5];   // (128,)
    float* out = (float*)d_out;                // (16,128,126,126)

    hyper_w_kernel<<<W_SIZE / 256, 256>>>(h, Wh, bh);
    hyper_b_kernel<<<BATCH, C_OUT>>>(h, Wb, bb);

    dim3 grid(64, C_OUT / TOC, BATCH);         // (spatial tiles, oc tiles, batch)
    conv_kernel<<<grid, 256>>>(x, out);
}

// round 2
// speedup vs baseline: 1.0054x; 1.0054x over previous
#include <cuda_runtime.h>

// ---------------- problem constants ----------------
#define BATCH   16
#define C_IN    128
#define C_OUT   128
#define KS      3
#define HH      128
#define WW      128
#define HDIM    512
#define W_SIZE  (C_OUT * C_IN * KS * KS)   // 147456
#define OH      126
#define OW      126

// ---------------- scratch (no runtime allocation allowed) ----------------
__device__ float g_w[BATCH * W_SIZE];   // per-sample conv weights, 9.4 MB
__device__ float g_b[BATCH * C_OUT];    // per-sample bias

// ============================================================
// Kernel A: w[b][n] = bh[n] + sum_k h[b][k] * Wh[n][k]
// One thread per n, all 16 batches accumulated in registers.
// h lives in SMEM (broadcast reads). Each lane walks its own Wh
// row sequentially in float4 steps -> full L1 line reuse, so DRAM
// traffic == 302 MB exactly.
// ============================================================
__global__ void __launch_bounds__(256) hyper_w_kernel(
    const float* __restrict__ h,
    const float* __restrict__ Wh,
    const float* __restrict__ bh)
{
    __shared__ __align__(16) float4 hs[BATCH][HDIM / 4];

    const int tid = threadIdx.x;
    const float4* h4 = (const float4*)h;
    #pragma unroll
    for (int i = tid; i < BATCH * HDIM / 4; i += 256)
        ((float4*)hs)[i] = h4[i];
    __syncthreads();

    const int n = blockIdx.x * 256 + tid;          // W_SIZE % 256 == 0
    const float4* w4 = (const float4*)Wh + (size_t)n * (HDIM / 4);

    float acc[BATCH];
    #pragma unroll
    for (int b = 0; b < BATCH; ++b) acc[b] = 0.f;

    #pragma unroll 4
    for (int k = 0; k < HDIM / 4; ++k) {
        const float4 wv = w4[k];
        #pragma unroll
        for (int b = 0; b < BATCH; ++b) {
            const float4 hv = hs[b][k];
            acc[b] += hv.x * wv.x + hv.y * wv.y + hv.z * wv.z + hv.w * wv.w;
        }
    }

    const float bias = bh[n];
    #pragma unroll
    for (int b = 0; b < BATCH; ++b)
        g_w[(size_t)b * W_SIZE + n] = acc[b] + bias;
}

// ============================================================
// Kernel B: b[b][oc] = bb[oc] + sum_k h[b][k] * Wb[oc][k]
// Tiny: grid = 16 blocks x 128 threads.
// ============================================================
__global__ void __launch_bounds__(128) hyper_b_kernel(
    const float* __restrict__ h,
    const float* __restrict__ Wb,
    const float* __restrict__ bb)
{
    const int b  = blockIdx.x;
    const int oc = threadIdx.x;
    const float4* h4 = (const float4*)(h + b * HDIM);
    const float4* w4 = (const float4*)(Wb + oc * HDIM);
    float s = 0.f;
    #pragma unroll 4
    for (int k = 0; k < HDIM / 4; ++k) {
        const float4 a = h4[k];
        const float4 w = w4[k];
        s += a.x * w.x + a.y * w.y + a.z * w.z + a.w * w.w;
    }
    g_b[b * C_OUT + oc] = s + bb[oc];
}

// ============================================================
// Kernel C: direct 3x3 VALID conv (cross-correlation), per-sample weights.
// Block: 32 output channels x 16x16 output pixels for one sample.
// ic processed in chunks of 16 through SMEM.
// Thread register tile: 4 oc x 8 px (32 accumulators).
// ============================================================
#define TOC 32          // oc per block
#define TP  16          // output tile edge
#define ICC 16          // ic per chunk
#define IROW 20         // padded smem input row (18 used)

__global__ void __launch_bounds__(256) conv_kernel(
    const float* __restrict__ x,
    float* __restrict__ out)
{
    __shared__ __align__(16) float in_s[ICC][TP + 2][IROW];    // 16*18*20*4 = 23040 B
    __shared__ float w_s[TOC][ICC * 9];                        // 32*144*4  = 18432 B

    const int tid  = threadIdx.x;
    const int b    = blockIdx.z;
    const int oc0  = blockIdx.y * TOC;
    const int tile = blockIdx.x;              // 0..63
    const int oh0  = (tile >> 3) * TP;
    const int ow0  = (tile & 7) * TP;

    const int tx  = tid & 31;
    const int ty  = tid >> 5;                 // 0..7
    const int pr  = tx >> 1;                  // 0..15  (output row in tile)
    const int pc  = (tx & 1) * 8;             // 0 or 8 (output col base)
    const int ocb = ty * 4;                   // oc offset within tile

    float acc[4][8];
    #pragma unroll
    for (int j = 0; j < 4; ++j)
        #pragma unroll
        for (int p = 0; p < 8; ++p) acc[j][p] = 0.f;

    const float* xb = x + (size_t)b * C_IN * HH * WW;
    const float* wb = g_w + (size_t)b * W_SIZE;

    for (int ic0 = 0; ic0 < C_IN; ic0 += ICC) {
        __syncthreads();   // previous chunk's compute done before overwrite

        // ---- stage input halo tile: ICC x 18 x 18 (guarded, coalesced) ----
        #pragma unroll
        for (int i = tid; i < ICC * 18 * 18; i += 256) {
            const int ic  = i / 324;
            const int rem = i - ic * 324;
            const int r   = rem / 18;
            const int c   = rem - r * 18;
            const int ih  = oh0 + r;
            const int iw  = ow0 + c;
            float v = 0.f;
            if (ih < HH && iw < WW)
                v = xb[(size_t)(ic0 + ic) * (HH * WW) + ih * WW + iw];
            in_s[ic][r][c] = v;
        }

        // ---- stage weights: TOC x (ICC*9), layout matches global (coalesced,
        //      conflict-free stores; compute reads are warp-uniform broadcasts) ----
        #pragma unroll
        for (int i = tid; i < TOC * ICC * 9; i += 256) {
            const int oc  = i / (ICC * 9);
            const int rem = i - oc * (ICC * 9);
            w_s[oc][rem] = wb[(size_t)(oc0 + oc) * (C_IN * 9) + ic0 * 9 + rem];
        }
        __syncthreads();

        // ---- compute ----
        #pragma unroll
        for (int ic = 0; ic < ICC; ++ic) {
            #pragma unroll
            for (int r = 0; r < 3; ++r) {
                // 10 input values cover 8 outputs x 3 horizontal taps
                const float* row = &in_s[ic][pr + r][pc];
                const float4 a0 = *(const float4*)(row);
                const float4 a1 = *(const float4*)(row + 4);
                const float2 a2 = *(const float2*)(row + 8);
                const float iv[10] = { a0.x, a0.y, a0.z, a0.w,
                                       a1.x, a1.y, a1.z, a1.w,
                                       a2.x, a2.y };
                #pragma unroll
                for (int c = 0; c < 3; ++c) {
                    const int widx = ic * 9 + r * 3 + c;
                    const float w0 = w_s[ocb + 0][widx];
                    const float w1 = w_s[ocb + 1][widx];
                    const float w2 = w_s[ocb + 2][widx];
                    const float w3 = w_s[ocb + 3][widx];
                    #pragma unroll
                    for (int p = 0; p < 8; ++p) {
                        const float xv = iv[p + c];
                        acc[0][p] += xv * w0;
                        acc[1][p] += xv * w1;
                        acc[2][p] += xv * w2;
                        acc[3][p] += xv * w3;
                    }
                }
            }
        }
    }

    // ---- epilogue: bias + guarded store ----
    const int oh = oh0 + pr;
    if (oh < OH) {
        #pragma unroll
        for (int j = 0; j < 4; ++j) {
            const int oc = oc0 + ocb + j;
            const float bias = g_b[b * C_OUT + oc];
            float* op = out + (((size_t)b * C_OUT + oc) * OH + oh) * OW + ow0 + pc;
            #pragma unroll
            for (int p = 0; p < 8; ++p) {
                if (ow0 + pc + p < OW)
                    op[p] = acc[j][p] + bias;
            }
        }
    }
}

// ============================================================
// launch
// ============================================================
extern "C" void kernel_launch(void* const* d_in, const int* in_sizes, int n_in,
                              void* d_out, int out_size)
{
    const float* x  = (const float*)d_in[0];   // (16,128,128,128)
    const float* h  = (const float*)d_in[1];   // (16,512)
    const float* Wh = (const float*)d_in[2];   // (147456,512)
    const float* bh = (const float*)d_in[3];   // (147456,)
    const float* Wb = (const float*)d_in[4];   // (128,512)
    const float* bb = (const float*)d_in[5];   // (128,)
    float* out = (float*)d_out;                // (16,128,126,126)

    hyper_w_kernel<<<W_SIZE / 256, 256>>>(h, Wh, bh);
    hyper_b_kernel<<<BATCH, C_OUT>>>(h, Wb, bb);

    dim3 grid(64, C_OUT / TOC, BATCH);         // (spatial tiles, oc tiles, batch)
    conv_kernel<<<grid, 256>>>(x, out);
}

// round 3
// speedup vs baseline: 1.0071x; 1.0017x over previous
#include <cuda_runtime.h>

// ---------------- problem constants ----------------
#define BATCH   16
#define C_IN    128
#define C_OUT   128
#define KS      3
#define HH      128
#define WW      128
#define HDIM    512
#define W_SIZE  (C_OUT * C_IN * KS * KS)   // 147456
#define OH      126
#define OW      126

// ---------------- scratch (no runtime allocation allowed) ----------------
__device__ float g_w[BATCH * W_SIZE];   // per-sample conv weights, 9.4 MB
__device__ float g_b[BATCH * C_OUT];    // per-sample bias

// ============================================================
// Kernel A: w[b][n] = bh[n] + sum_k h[b][k] * Wh[n][k]
// One thread per n, all 16 batches accumulated in registers.
// h lives in SMEM (broadcast reads). Each lane walks its own Wh
// row sequentially in float4 steps -> full L1 line reuse, so DRAM
// traffic == 302 MB exactly.
// ============================================================
__global__ void __launch_bounds__(256) hyper_w_kernel(
    const float* __restrict__ h,
    const float* __restrict__ Wh,
    const float* __restrict__ bh)
{
    __shared__ __align__(16) float4 hs[BATCH][HDIM / 4];

    const int tid = threadIdx.x;
    const float4* h4 = (const float4*)h;
    #pragma unroll
    for (int i = tid; i < BATCH * HDIM / 4; i += 256)
        ((float4*)hs)[i] = h4[i];
    __syncthreads();

    const int n = blockIdx.x * 256 + tid;          // W_SIZE % 256 == 0
    const float4* w4 = (const float4*)Wh + (size_t)n * (HDIM / 4);

    float acc[BATCH];
    #pragma unroll
    for (int b = 0; b < BATCH; ++b) acc[b] = 0.f;

    #pragma unroll 4
    for (int k = 0; k < HDIM / 4; ++k) {
        const float4 wv = w4[k];
        #pragma unroll
        for (int b = 0; b < BATCH; ++b) {
            const float4 hv = hs[b][k];
            acc[b] += hv.x * wv.x + hv.y * wv.y + hv.z * wv.z + hv.w * wv.w;
        }
    }

    const float bias = bh[n];
    #pragma unroll
    for (int b = 0; b < BATCH; ++b)
        g_w[(size_t)b * W_SIZE + n] = acc[b] + bias;
}

// ============================================================
// Kernel B: b[b][oc] = bb[oc] + sum_k h[b][k] * Wb[oc][k]
// Tiny: grid = 16 blocks x 128 threads.
// ============================================================
__global__ void __launch_bounds__(128) hyper_b_kernel(
    const float* __restrict__ h,
    const float* __restrict__ Wb,
    const float* __restrict__ bb)
{
    const int b  = blockIdx.x;
    const int oc = threadIdx.x;
    const float4* h4 = (const float4*)(h + b * HDIM);
    const float4* w4 = (const float4*)(Wb + oc * HDIM);
    float s = 0.f;
    #pragma unroll 4
    for (int k = 0; k < HDIM / 4; ++k) {
        const float4 a = h4[k];
        const float4 w = w4[k];
        s += a.x * w.x + a.y * w.y + a.z * w.z + a.w * w.w;
    }
    g_b[b * C_OUT + oc] = s + bb[oc];
}

// ============================================================
// Kernel C: direct 3x3 VALID conv (cross-correlation), per-sample weights.
// Block: 32 output channels x 16x16 output pixels for one sample.
// ic processed in chunks of 16 through SMEM.
// Thread register tile: 4 oc x 8 px (32 accumulators).
// ============================================================
#define TOC 32          // oc per block
#define TP  16          // output tile edge
#define ICC 16          // ic per chunk
#define IROW 20         // padded smem input row (18 used)

__global__ void __launch_bounds__(256) conv_kernel(
    const float* __restrict__ x,
    float* __restrict__ out)
{
    __shared__ __align__(16) float in_s[ICC][TP + 2][IROW];    // 16*18*20*4 = 23040 B
    __shared__ float w_s[TOC][ICC * 9];                        // 32*144*4  = 18432 B

    const int tid  = threadIdx.x;
    const int b    = blockIdx.z;
    const int oc0  = blockIdx.y * TOC;
    const int tile = blockIdx.x;              // 0..63
    const int oh0  = (tile >> 3) * TP;
    const int ow0  = (tile & 7) * TP;

    const int tx  = tid & 31;
    const int ty  = tid >> 5;                 // 0..7
    const int pr  = tx >> 1;                  // 0..15  (output row in tile)
    const int pc  = (tx & 1) * 8;             // 0 or 8 (output col base)
    const int ocb = ty * 4;                   // oc offset within tile

    float acc[4][8];
    #pragma unroll
    for (int j = 0; j < 4; ++j)
        #pragma unroll
        for (int p = 0; p < 8; ++p) acc[j][p] = 0.f;

    const float* xb = x + (size_t)b * C_IN * HH * WW;
    const float* wb = g_w + (size_t)b * W_SIZE;

    for (int ic0 = 0; ic0 < C_IN; ic0 += ICC) {
        __syncthreads();   // previous chunk's compute done before overwrite

        // ---- stage input halo tile: ICC x 18 x 18 (guarded, coalesced) ----
        #pragma unroll
        for (int i = tid; i < ICC * 18 * 18; i += 256) {
            const int ic  = i / 324;
            const int rem = i - ic * 324;
            const int r   = rem / 18;
            const int c   = rem - r * 18;
            const int ih  = oh0 + r;
            const int iw  = ow0 + c;
            float v = 0.f;
            if (ih < HH && iw < WW)
                v = xb[(size_t)(ic0 + ic) * (HH * WW) + ih * WW + iw];
            in_s[ic][r][c] = v;
        }

        // ---- stage weights: TOC x (ICC*9), layout matches global (coalesced,
        //      conflict-free stores; compute reads are warp-uniform broadcasts) ----
        #pragma unroll
        for (int i = tid; i < TOC * ICC * 9; i += 256) {
            const int oc  = i / (ICC * 9);
            const int rem = i - oc * (ICC * 9);
            w_s[oc][rem] = wb[(size_t)(oc0 + oc) * (C_IN * 9) + ic0 * 9 + rem];
        }
        __syncthreads();

        // ---- compute ----
        #pragma unroll
        for (int ic = 0; ic < ICC; ++ic) {
            #pragma unroll
            for (int r = 0; r < 3; ++r) {
                // 10 input values cover 8 outputs x 3 horizontal taps
                const float* row = &in_s[ic][pr + r][pc];
                const float4 a0 = *(const float4*)(row);
                const float4 a1 = *(const float4*)(row + 4);
                const float2 a2 = *(const float2*)(row + 8);
                const float iv[10] = { a0.x, a0.y, a0.z, a0.w,
                                       a1.x, a1.y, a1.z, a1.w,
                                       a2.x, a2.y };
                #pragma unroll
                for (int c = 0; c < 3; ++c) {
                    const int widx = ic * 9 + r * 3 + c;
                    const float w0 = w_s[ocb + 0][widx];
                    const float w1 = w_s[ocb + 1][widx];
                    const float w2 = w_s[ocb + 2][widx];
                    const float w3 = w_s[ocb + 3][widx];
                    #pragma unroll
                    for (int p = 0; p < 8; ++p) {
                        const float xv = iv[p + c];
                        acc[0][p] += xv * w0;
                        acc[1][p] += xv * w1;
                        acc[2][p] += xv * w2;
                        acc[3][p] += xv * w3;
                    }
                }
            }
        }
    }

    // ---- epilogue: bias + guarded store ----
    const int oh = oh0 + pr;
    if (oh < OH) {
        #pragma unroll
        for (int j = 0; j < 4; ++j) {
            const int oc = oc0 + ocb + j;
            const float bias = g_b[b * C_OUT + oc];
            float* op = out + (((size_t)b * C_OUT + oc) * OH + oh) * OW + ow0 + pc;
            #pragma unroll
            for (int p = 0; p < 8; ++p) {
                if (ow0 + pc + p < OW)
                    op[p] = acc[j][p] + bias;
            }
        }
    }
}

// ============================================================
// launch
// ============================================================
extern "C" void kernel_launch(void* const* d_in, const int* in_sizes, int n_in,
                              void* d_out, int out_size)
{
    const float* x  = (const float*)d_in[0];   // (16,128,128,128)
    const float* h  = (const float*)d_in[1];   // (16,512)
    const float* Wh = (const float*)d_in[2];   // (147456,512)
    const float* bh = (const float*)d_in[3];   // (147456,)
    const float* Wb = (const float*)d_in[4];   // (128,512)
    const float* bb = (const float*)d_in[5];   // (128,)
    float* out = (float*)d_out;                // (16,128,126,126)

    hyper_w_kernel<<<W_SIZE / 256, 256>>>(h, Wh, bh);
    hyper_b_kernel<<<BATCH, C_OUT>>>(h, Wb, bb);

    dim3 grid(64, C_OUT / TOC, BATCH);         // (spatial tiles, oc tiles, batch)
    conv_kernel<<<grid, 256>>>(x, out);
}